// round 17
// baseline (speedup 1.0000x reference)
#include <cuda_runtime.h>
#include <cuda_bf16.h>
#include <cuda_fp16.h>
#include <math.h>
#include <stdint.h>

#define NLAYER 12
#define EPSV 1e-5f
typedef unsigned short u16;

// ---------------- f32 scratch ------------------------------------------------
__device__ float g_e  [1048576];
__device__ float g_q  [1048576];
__device__ float g_big[4194304];
__device__ float g_s  [8388608];
__device__ float g_rowsum[16384];

// ---------------- weight fp16 hi/lo ------------------------------------------
#define OFF_E1 0L
#define OFF_E2 1048576L
#define OFF_EI 1572864L
#define OFF_Q  2621440L
#define OFF_K  8912896L
#define OFF_V  15204352L
#define OFF_O  21495808L
#define OFF_F1 27787264L
#define OFF_F2 52953088L
#define OFF_D1 78118912L
#define OFF_D2 79167488L
#define OFF_DI 81264640L
#define W_TOT  82313216L
__device__ u16 g_wh[W_TOT];
__device__ u16 g_wl[W_TOT];
// combined (dw-folded) QKV weights: [i][proj][d][m][c*512+k], K=1024
#define CQ_TOT 37748736L
__device__ u16 g_cqh[CQ_TOT];
__device__ u16 g_cql[CQ_TOT];
// fp16 single activations
__device__ u16 g_ath[4194304];
__device__ u16 g_hth[1048576];
__device__ u16 g_oth[1048576];
// attention operands
__device__ u16 g_qth[1048576], g_qtl[1048576];   // bf16 hi/lo
__device__ u16 g_kth[1048576], g_ktl[1048576];   // bf16 hi/lo
__device__ u16 g_vh [1048576], g_vl [1048576];   // fp16 hi/lo
__device__ u16 g_ph [8388608];                   // fp16 unnormalized expS

// ---------------- helpers ----------------------------------------------------
__device__ __forceinline__ uint32_t smem_u32(const void* p) {
    uint32_t a;
    asm("{ .reg .u64 t; cvta.to.shared.u64 t, %1; cvt.u32.u64 %0, t; }" : "=r"(a) : "l"(p));
    return a;
}
#define SWZ(x) ((x) ^ (((x) >> 3) & 0x70))

__device__ __forceinline__ void cp16(uint32_t d, const void* g) {
    asm volatile("cp.async.cg.shared.global [%0], [%1], 16;" :: "r"(d), "l"(g));
}
__device__ __forceinline__ void cp_commit() { asm volatile("cp.async.commit_group;"); }
template<int N> __device__ __forceinline__ void cp_wait() {
    asm volatile("cp.async.wait_group %0;" :: "n"(N));
}
__device__ __forceinline__ void ldsm4(uint32_t* r, uint32_t a) {
    asm volatile("ldmatrix.sync.aligned.m8n8.x4.shared.b16 {%0,%1,%2,%3}, [%4];"
                 : "=r"(r[0]), "=r"(r[1]), "=r"(r[2]), "=r"(r[3]) : "r"(a));
}
__device__ __forceinline__ void mma_bf(float* c, const uint32_t* a, const uint32_t* b) {
    asm volatile(
        "mma.sync.aligned.m16n8k16.row.col.f32.bf16.bf16.f32 "
        "{%0,%1,%2,%3}, {%4,%5,%6,%7}, {%8,%9}, {%0,%1,%2,%3};"
        : "+f"(c[0]), "+f"(c[1]), "+f"(c[2]), "+f"(c[3])
        : "r"(a[0]), "r"(a[1]), "r"(a[2]), "r"(a[3]), "r"(b[0]), "r"(b[1]));
}
__device__ __forceinline__ void mma_fp(float* c, const uint32_t* a, const uint32_t* b) {
    asm volatile(
        "mma.sync.aligned.m16n8k16.row.col.f32.f16.f16.f32 "
        "{%0,%1,%2,%3}, {%4,%5,%6,%7}, {%8,%9}, {%0,%1,%2,%3};"
        : "+f"(c[0]), "+f"(c[1]), "+f"(c[2]), "+f"(c[3])
        : "r"(a[0]), "r"(a[1]), "r"(a[2]), "r"(a[3]), "r"(b[0]), "r"(b[1]));
}
__device__ __forceinline__ void splt(float v, u16& h, u16& l) {   // bf16 hi/lo
    __nv_bfloat16 hb = __float2bfloat16(v);
    h = __bfloat16_as_ushort(hb);
    l = __bfloat16_as_ushort(__float2bfloat16(v - __bfloat162float(hb)));
}
__device__ __forceinline__ void splth(float v, u16& h, u16& l) {  // fp16 hi/lo
    __half hh = __float2half(v);
    h = __half_as_ushort(hh);
    l = __half_as_ushort(__float2half(v - __half2float(hh)));
}
__device__ __forceinline__ u16 f2h(float v) { return __half_as_ushort(__float2half(v)); }

// bf16 3-term chunk: acc += Ah*Bh + Ah*Bl + Al*Bh
template<int NT>
__device__ __forceinline__ void mma_chunk(
    float (&acc)[2][NT][4], uint32_t aHi, uint32_t aLo, uint32_t bHi, uint32_t bLo,
    int wm, int wn, int lane)
{
    int la = lane & 7, j = lane >> 3;
    #pragma unroll
    for (int ks = 0; ks < 4; ks++) {
        uint32_t ah[2][4], al[2][4];
        #pragma unroll
        for (int mi = 0; mi < 2; mi++) {
            uint32_t off = SWZ((uint32_t)((wm * 32 + mi * 16 + ((j & 1) << 3) + la) * 128 + ks * 32 + ((j >> 1) << 4)));
            ldsm4(ah[mi], aHi + off);
            ldsm4(al[mi], aLo + off);
        }
        uint32_t bh[NT][2], bl[NT][2];
        #pragma unroll
        for (int nt = 0; nt < NT; nt += 2) {
            uint32_t off = SWZ((uint32_t)((wn * NT * 8 + nt * 8 + ((j >> 1) << 3) + la) * 128 + ks * 32 + ((j & 1) << 4)));
            uint32_t t[4];
            ldsm4(t, bHi + off);
            bh[nt][0] = t[0]; bh[nt][1] = t[1]; bh[nt + 1][0] = t[2]; bh[nt + 1][1] = t[3];
            ldsm4(t, bLo + off);
            bl[nt][0] = t[0]; bl[nt][1] = t[1]; bl[nt + 1][0] = t[2]; bl[nt + 1][1] = t[3];
        }
        #pragma unroll
        for (int mi = 0; mi < 2; mi++)
            #pragma unroll
            for (int nt = 0; nt < NT; nt++) {
                mma_bf(acc[mi][nt], ah[mi], bh[nt]);
                mma_bf(acc[mi][nt], ah[mi], bl[nt]);
                mma_bf(acc[mi][nt], al[mi], bh[nt]);
            }
    }
}

// fp16 2-term, A hi/lo x B single
template<int NT>
__device__ __forceinline__ void mma2_chunk(
    float (&acc)[2][NT][4], uint32_t aHi, uint32_t aLo, uint32_t bS,
    int wm, int wn, int lane)
{
    int la = lane & 7, j = lane >> 3;
    #pragma unroll
    for (int ks = 0; ks < 4; ks++) {
        uint32_t ah[2][4], al[2][4];
        #pragma unroll
        for (int mi = 0; mi < 2; mi++) {
            uint32_t off = SWZ((uint32_t)((wm * 32 + mi * 16 + ((j & 1) << 3) + la) * 128 + ks * 32 + ((j >> 1) << 4)));
            ldsm4(ah[mi], aHi + off);
            ldsm4(al[mi], aLo + off);
        }
        uint32_t bh[NT][2];
        #pragma unroll
        for (int nt = 0; nt < NT; nt += 2) {
            uint32_t off = SWZ((uint32_t)((wn * NT * 8 + nt * 8 + ((j >> 1) << 3) + la) * 128 + ks * 32 + ((j & 1) << 4)));
            uint32_t t[4];
            ldsm4(t, bS + off);
            bh[nt][0] = t[0]; bh[nt][1] = t[1]; bh[nt + 1][0] = t[2]; bh[nt + 1][1] = t[3];
        }
        #pragma unroll
        for (int mi = 0; mi < 2; mi++)
            #pragma unroll
            for (int nt = 0; nt < NT; nt++) {
                mma_fp(acc[mi][nt], ah[mi], bh[nt]);
                mma_fp(acc[mi][nt], al[mi], bh[nt]);
            }
    }
}

// fp16 2-term, A single x B hi/lo
template<int NT>
__device__ __forceinline__ void mma2b_chunk(
    float (&acc)[2][NT][4], uint32_t aS, uint32_t bHi, uint32_t bLo,
    int wm, int wn, int lane)
{
    int la = lane & 7, j = lane >> 3;
    #pragma unroll
    for (int ks = 0; ks < 4; ks++) {
        uint32_t ah[2][4];
        #pragma unroll
        for (int mi = 0; mi < 2; mi++) {
            uint32_t off = SWZ((uint32_t)((wm * 32 + mi * 16 + ((j & 1) << 3) + la) * 128 + ks * 32 + ((j >> 1) << 4)));
            ldsm4(ah[mi], aS + off);
        }
        uint32_t bh[NT][2], bl[NT][2];
        #pragma unroll
        for (int nt = 0; nt < NT; nt += 2) {
            uint32_t off = SWZ((uint32_t)((wn * NT * 8 + nt * 8 + ((j >> 1) << 3) + la) * 128 + ks * 32 + ((j & 1) << 4)));
            uint32_t t[4];
            ldsm4(t, bHi + off);
            bh[nt][0] = t[0]; bh[nt][1] = t[1]; bh[nt + 1][0] = t[2]; bh[nt + 1][1] = t[3];
            ldsm4(t, bLo + off);
            bl[nt][0] = t[0]; bl[nt][1] = t[1]; bl[nt + 1][0] = t[2]; bl[nt + 1][1] = t[3];
        }
        #pragma unroll
        for (int mi = 0; mi < 2; mi++)
            #pragma unroll
            for (int nt = 0; nt < NT; nt++) {
                mma_fp(acc[mi][nt], ah[mi], bh[nt]);
                mma_fp(acc[mi][nt], ah[mi], bl[nt]);
            }
    }
}

// ---------------- one-time weight split --------------------------------------
__global__ void __launch_bounds__(256) split_w(
    const float* p0, const float* p1, const float* p2, const float* p3,
    const float* p4, const float* p5, const float* p6, const float* p7,
    const float* p8, const float* p9, const float* p10, const float* p11)
{
    const long offs[12] = {OFF_E1, OFF_E2, OFF_EI, OFF_Q, OFF_K, OFF_V,
                           OFF_O, OFF_F1, OFF_F2, OFF_D1, OFF_D2, OFF_DI};
    const float* ptrs[12] = {p0, p1, p2, p3, p4, p5, p6, p7, p8, p9, p10, p11};
    long base = ((long)blockIdx.x * 256 + threadIdx.x) * 16;
    if (base >= W_TOT) return;
    int seg = 0;
    #pragma unroll
    for (int i = 1; i < 12; i++) if (base >= offs[i]) seg = i;
    const float* src = ptrs[seg] + (base - offs[seg]);
    u16 hb[16], lb[16];
    #pragma unroll
    for (int t = 0; t < 16; t += 4) {
        float4 x = *reinterpret_cast<const float4*>(src + t);
        splth(x.x, hb[t], lb[t]); splth(x.y, hb[t+1], lb[t+1]);
        splth(x.z, hb[t+2], lb[t+2]); splth(x.w, hb[t+3], lb[t+3]);
    }
    uint4* dh = reinterpret_cast<uint4*>(&g_wh[base]);
    uint4* dl = reinterpret_cast<uint4*>(&g_wl[base]);
    dh[0] = ((uint4*)hb)[0]; dh[1] = ((uint4*)hb)[1];
    dl[0] = ((uint4*)lb)[0]; dl[1] = ((uint4*)lb)[1];
}

// ---------------- one-time combined QKV weight build --------------------------
// cq[i][proj][d][m][c*512+k] = dw[i][proj][d][c] * w[i][proj][c][m][k]
__global__ void __launch_bounds__(256) split_qkv(
    const float* qpw, const float* kpw, const float* vpw,
    const float* qdw, const float* kdw, const float* vdw)
{
    long R = (long)blockIdx.x * 4 + (threadIdx.x >> 6);   // row 0..36863
    int k2 = (threadIdx.x & 63) * 16;
    int m = (int)(R & 511);
    int d = (int)((R >> 9) & 1);
    long ip = R >> 10;
    int proj = (int)(ip % 3);
    int i = (int)(ip / 3);
    int c = k2 >> 9, k0 = k2 & 511;
    const float* pw = proj == 0 ? qpw : (proj == 1 ? kpw : vpw);
    const float* dw = proj == 0 ? qdw : (proj == 1 ? kdw : vdw);
    float scale = dw[i * 4 + d * 2 + c];
    const float* src = pw + ((size_t)(i * 2 + c) * 512 + m) * 512 + k0;
    u16 hb[16], lb[16];
    #pragma unroll
    for (int t = 0; t < 16; t += 4) {
        float4 x = *reinterpret_cast<const float4*>(src + t);
        splth(scale * x.x, hb[t], lb[t]); splth(scale * x.y, hb[t+1], lb[t+1]);
        splth(scale * x.z, hb[t+2], lb[t+2]); splth(scale * x.w, hb[t+3], lb[t+3]);
    }
    size_t o = (size_t)R * 1024 + k2;
    uint4* dh = reinterpret_cast<uint4*>(&g_cqh[o]);
    uint4* dl = reinterpret_cast<uint4*>(&g_cql[o]);
    dh[0] = ((uint4*)hb)[0]; dh[1] = ((uint4*)hb)[1];
    dl[0] = ((uint4*)lb)[0]; dl[1] = ((uint4*)lb)[1];
}

// ---------------- transpose to single fp16 (old [z][w][R] layout) -------------
__global__ void __launch_bounds__(256) tsplit(
    const float* __restrict__ X, u16* __restrict__ Th, int R)
{
    __shared__ float s[64][65];
    int tid = threadIdx.x;
    int z = blockIdx.z, f0 = blockIdx.y * 64, w0 = blockIdx.x * 64;
    const float* Xb = X + ((size_t)z * R + f0) * 512 + w0;
    for (int it = tid; it < 1024; it += 256) {
        int r = it >> 4, cg = it & 15;
        float4 v = *reinterpret_cast<const float4*>(Xb + (size_t)r * 512 + cg * 4);
        s[r][cg * 4 + 0] = v.x; s[r][cg * 4 + 1] = v.y;
        s[r][cg * 4 + 2] = v.z; s[r][cg * 4 + 3] = v.w;
    }
    __syncthreads();
    for (int it = tid; it < 512; it += 256) {
        int w = it >> 3, cg = it & 7;
        u16 hb[8];
        #pragma unroll
        for (int j = 0; j < 8; j++) hb[j] = f2h(s[cg * 8 + j][w]);
        size_t o = ((size_t)z * 512 + w0 + w) * R + f0 + cg * 8;
        *reinterpret_cast<uint4*>(Th + o) = *reinterpret_cast<uint4*>(hb);
    }
}

// ---------------- frame_norm + transpose -> [b][w][c*512+f] ; zero rowsum ----
__global__ void __launch_bounds__(256) fn_tsplit(
    const float* __restrict__ X, const float* __restrict__ gw, const float* __restrict__ gb,
    u16* __restrict__ Th, float* __restrict__ rowsum)
{
    int tid = threadIdx.x;
    int gi = ((int)(blockIdx.z * 64 + blockIdx.y * 8 + blockIdx.x)) * 256 + tid;
    if (gi < 16384) rowsum[gi] = 0.f;
    int bc = blockIdx.z, c = bc & 1, b = bc >> 1;
    int w0 = blockIdx.x * 64;
    int ft = blockIdx.y;
    const float* Xb = X + (size_t)bc * 262144;

    int wl = tid & 63, part = tid >> 6;
    float sum = 0.f, sq = 0.f;
    for (int f = part; f < 512; f += 4) {
        float v = Xb[(size_t)f * 512 + w0 + wl];
        sum += v; sq += v * v;
    }
    __shared__ float r1[4][64], r2[4][64];
    __shared__ float smu[64], srs[64];
    r1[part][wl] = sum; r2[part][wl] = sq;
    __syncthreads();
    if (tid < 64) {
        float s = r1[0][tid] + r1[1][tid] + r1[2][tid] + r1[3][tid];
        float q = r2[0][tid] + r2[1][tid] + r2[2][tid] + r2[3][tid];
        float mu = s * (1.f / 512.f);
        float var = q * (1.f / 512.f) - mu * mu;
        smu[tid] = mu; srs[tid] = rsqrtf(var + EPSV);
    }
    __syncthreads();

    __shared__ float tile[64][65];
    for (int it = tid; it < 1024; it += 256) {
        int r = it >> 4, cg = it & 15;
        float4 v = *reinterpret_cast<const float4*>(Xb + (size_t)(ft * 64 + r) * 512 + w0 + cg * 4);
        tile[r][cg * 4 + 0] = v.x; tile[r][cg * 4 + 1] = v.y;
        tile[r][cg * 4 + 2] = v.z; tile[r][cg * 4 + 3] = v.w;
    }
    __syncthreads();
    int w = tid >> 2, seg = tid & 3;
    float mu = smu[w], rs = srs[w];
    u16 hb[16];
    #pragma unroll
    for (int j = 0; j < 16; j++) {
        int f = seg * 16 + j, fg = ft * 64 + f;
        hb[j] = f2h((tile[f][w] - mu) * rs * gw[c * 512 + fg] + gb[c * 512 + fg]);
    }
    size_t o = ((size_t)b * 512 + w0 + w) * 1024 + c * 512 + ft * 64 + seg * 16;
    reinterpret_cast<uint4*>(Th + o)[0] = ((uint4*)hb)[0];
    reinterpret_cast<uint4*>(Th + o)[1] = ((uint4*)hb)[1];
}

// ---------------- fused QKV GEMM: K=1024, epilogue rope/V-split --------------
__global__ void __launch_bounds__(256, 2) gemm_qkv(
    const u16* __restrict__ Ah, const u16* __restrict__ Al,
    const u16* __restrict__ Bs,
    u16* __restrict__ Qh, u16* __restrict__ Ql,
    u16* __restrict__ Kh, u16* __restrict__ Kl,
    u16* __restrict__ Vh, u16* __restrict__ Vl)
{
    constexpr int STG = 16384 + 16384;
    extern __shared__ char sm[];
    uint32_t sb = smem_u32(sm);
    int tid = threadIdx.x, wid = tid >> 5, lane = tid & 31;
    int wm = wid >> 2, wn = wid & 3;
    int z = blockIdx.z;                         // proj*4 + b*2 + d
    int proj = z >> 2, b = (z >> 1) & 1, d = z & 1, bd = z & 3;
    const u16* Ab_h = Ah + ((size_t)(proj * 2 + d) * 512) * 1024;
    const u16* Ab_l = Al + ((size_t)(proj * 2 + d) * 512) * 1024;
    const u16* Bb = Bs + (size_t)b * 524288;
    int m0 = blockIdx.y * 64, n0 = blockIdx.x * 128;

    auto load_stage = [&](int ch, int s) {
        uint32_t st = sb + s * STG;
        const u16* ah = Ab_h + (size_t)m0 * 1024 + ch * 64;
        const u16* al = Ab_l + (size_t)m0 * 1024 + ch * 64;
        for (int it = tid; it < 512; it += 256) {
            int r = it >> 3, cg = it & 7;
            uint32_t o = SWZ((uint32_t)(r * 128 + cg * 16));
            size_t gof = (size_t)r * 1024 + cg * 8;
            cp16(st + o, ah + gof);
            cp16(st + 8192 + o, al + gof);
        }
        const u16* bh = Bb + (size_t)n0 * 1024 + ch * 64;
        for (int it = tid; it < 1024; it += 256) {
            int r = it >> 3, cg = it & 7;
            uint32_t o = SWZ((uint32_t)(r * 128 + cg * 16));
            cp16(st + 16384 + o, bh + (size_t)r * 1024 + cg * 8);
        }
    };

    float acc[2][4][4] = {};
    load_stage(0, 0); cp_commit();
    for (int ch = 0; ch < 16; ch++) {
        if (ch + 1 < 16) { load_stage(ch + 1, (ch + 1) & 1); cp_commit(); cp_wait<1>(); }
        else cp_wait<0>();
        __syncthreads();
        uint32_t st = sb + (ch & 1) * STG;
        mma2_chunk<4>(acc, st, st + 8192, st + 16384, wm, wn, lane);
        __syncthreads();
    }

    float* stg = (float*)sm;  // 64 x 132
    #pragma unroll
    for (int mi = 0; mi < 2; mi++)
        #pragma unroll
        for (int nt = 0; nt < 4; nt++) {
            int row = wm * 32 + mi * 16 + (lane >> 2);
            int col = wn * 32 + nt * 8 + (lane & 3) * 2;
            stg[row * 132 + col] = acc[mi][nt][0];
            stg[row * 132 + col + 1] = acc[mi][nt][1];
            stg[(row + 8) * 132 + col] = acc[mi][nt][2];
            stg[(row + 8) * 132 + col + 1] = acc[mi][nt][3];
        }
    __syncthreads();

    if (proj < 2) {
        // RoPE + transpose -> bf16 hi/lo [bd][w][f]
        int j = tid >> 1, msel = tid & 1;
        int wg = n0 + j;
        u16 hb[32], lb[32];
        #pragma unroll
        for (int t = 0; t < 16; t++) {
            int fl = msel * 32 + t * 2;
            float v0 = stg[fl * 132 + j];
            float v1 = stg[(fl + 1) * 132 + j];
            int fg = m0 + fl;
            int ir = (fg & 63) >> 1;
            float inv = powf(10000.f, -(float)(2 * ir) / 64.f);
            float sn, cs;
            sincosf((float)wg * inv, &sn, &cs);
            splt(v0 * cs - v1 * sn, hb[t * 2], lb[t * 2]);
            splt(v1 * cs + v0 * sn, hb[t * 2 + 1], lb[t * 2 + 1]);
        }
        u16* Th = proj ? Kh : Qh;
        u16* Tl = proj ? Kl : Ql;
        size_t o = ((size_t)bd * 512 + wg) * 512 + m0 + msel * 32;
        #pragma unroll
        for (int t = 0; t < 4; t++) {
            reinterpret_cast<uint4*>(Th + o)[t] = ((uint4*)hb)[t];
            reinterpret_cast<uint4*>(Tl + o)[t] = ((uint4*)lb)[t];
        }
    } else {
        // V natural [bd][f][w], fp16 hi/lo
        int row = tid >> 2, dseg = tid & 3;
        u16 hb[32], lb[32];
        #pragma unroll
        for (int j = 0; j < 32; j++)
            splth(stg[row * 132 + dseg * 32 + j], hb[j], lb[j]);
        size_t o = ((size_t)bd * 512 + m0 + row) * 512 + n0 + dseg * 32;
        #pragma unroll
        for (int t = 0; t < 4; t++) {
            reinterpret_cast<uint4*>(Vh + o)[t] = ((uint4*)hb)[t];
            reinterpret_cast<uint4*>(Vl + o)[t] = ((uint4*)lb)[t];
        }
    }
}

// ---------------- pipelined fp16 2-term weight GEMM (param B strides) --------
template<int OUT, int NT>  // OUT: 0 f32 ; 2 f32+res ; 3 sqrelu -> fp16 CT (NT=4)
__global__ void __launch_bounds__(256, 2) gemm_bb(
    const u16* __restrict__ Ah, const u16* __restrict__ Al,
    const u16* __restrict__ Bs,
    const float* __restrict__ Res, float* __restrict__ C,
    u16* __restrict__ CT,
    int M, int K, int ldB, long sbB, long scB)
{
    constexpr int BN = NT * 32;
    constexpr int BSZ = BN * 128;
    constexpr int STG = 16384 + BSZ;
    extern __shared__ char sm[];
    uint32_t sb = smem_u32(sm);
    int tid = threadIdx.x, wid = tid >> 5, lane = tid & 31;
    int wm = wid >> 2, wn = wid & 3;
    int bc = blockIdx.z, c = bc & 1;
    const u16* Ab_h = Ah + (size_t)c * M * K;
    const u16* Ab_l = Al + (size_t)c * M * K;
    const u16* Bb = Bs + (size_t)(bc >> 1) * sbB + (size_t)c * scB;
    int m0 = blockIdx.y * 64, n0 = blockIdx.x * BN;

    auto load_stage = [&](int ch, int s) {
        uint32_t st = sb + s * STG;
        const u16* ah = Ab_h + (size_t)m0 * K + ch * 64;
        const u16* al = Ab_l + (size_t)m0 * K + ch * 64;
        for (int it = tid; it < 512; it += 256) {
            int r = it >> 3, cg = it & 7;
            uint32_t o = SWZ((uint32_t)(r * 128 + cg * 16));
            size_t gof = (size_t)r * K + cg * 8;
            cp16(st + o, ah + gof);
            cp16(st + 8192 + o, al + gof);
        }
        const u16* bh = Bb + (size_t)n0 * ldB + ch * 64;
        for (int it = tid; it < BN * 8; it += 256) {
            int r = it >> 3, cg = it & 7;
            uint32_t o = SWZ((uint32_t)(r * 128 + cg * 16));
            cp16(st + 16384 + o, bh + (size_t)r * ldB + cg * 8);
        }
    };

    float acc[2][NT][4] = {};
    int NC = K >> 6;
    load_stage(0, 0); cp_commit();
    for (int ch = 0; ch < NC; ch++) {
        if (ch + 1 < NC) { load_stage(ch + 1, (ch + 1) & 1); cp_commit(); cp_wait<1>(); }
        else cp_wait<0>();
        __syncthreads();
        uint32_t st = sb + (ch & 1) * STG;
        mma2_chunk<NT>(acc, st, st + 8192, st + 16384, wm, wn, lane);
        __syncthreads();
    }

    float* stg = (float*)sm;  // 64 x (BN+4)
    #pragma unroll
    for (int mi = 0; mi < 2; mi++)
        #pragma unroll
        for (int nt = 0; nt < NT; nt++) {
            int row = wm * 32 + mi * 16 + (lane >> 2);
            int col = wn * NT * 8 + nt * 8 + (lane & 3) * 2;
            stg[row * (BN + 4) + col] = acc[mi][nt][0];
            stg[row * (BN + 4) + col + 1] = acc[mi][nt][1];
            stg[(row + 8) * (BN + 4) + col] = acc[mi][nt][2];
            stg[(row + 8) * (BN + 4) + col + 1] = acc[mi][nt][3];
        }
    __syncthreads();

    if (OUT == 3) {
        int j = tid >> 1, msel = tid & 1;
        u16 hb[32];
        #pragma unroll
        for (int i = 0; i < 32; i++) {
            float v = stg[(msel * 32 + i) * (BN + 4) + j];
            float r = fmaxf(v, 0.f);
            hb[i] = f2h(r * r);
        }
        size_t o = ((size_t)bc * 512 + n0 + j) * (size_t)M + m0 + msel * 32;
        #pragma unroll
        for (int t = 0; t < 4; t++)
            reinterpret_cast<uint4*>(CT + o)[t] = ((uint4*)hb)[t];
    } else {
        float* Cb = C + (size_t)bc * M * 512;
        constexpr int CPR = BN / 4;
        #pragma unroll
        for (int it = 0; it < 64 * CPR / 256; it++) {
            int idx = it * 256 + tid;
            int row = idx / CPR, c4 = idx % CPR;
            float4 v = *reinterpret_cast<float4*>(stg + row * (BN + 4) + c4 * 4);
            float vv[4] = {v.x, v.y, v.z, v.w};
            if (OUT == 2) {
                float4 rv = *reinterpret_cast<const float4*>(
                    Res + (size_t)bc * M * 512 + (size_t)(m0 + row) * 512 + n0 + c4 * 4);
                vv[0] += rv.x; vv[1] += rv.y; vv[2] += rv.z; vv[3] += rv.w;
            }
            float4 ov = {vv[0], vv[1], vv[2], vv[3]};
            *reinterpret_cast<float4*>(Cb + (size_t)(m0 + row) * 512 + n0 + c4 * 4) = ov;
        }
    }
}

// ---------------- attention scores -> exp -> unnormalized P fp16 -------------
__global__ void __launch_bounds__(256, 2) attn_qk_bb(
    const u16* __restrict__ QTh, const u16* __restrict__ QTl,
    const u16* __restrict__ KTh, const u16* __restrict__ KTl,
    u16* __restrict__ Ph, float* __restrict__ rowsum)
{
    __shared__ char sm[49152];
    uint32_t sb = smem_u32(sm);
    int tid = threadIdx.x, wid = tid >> 5, lane = tid & 31;
    int wm = wid >> 2, wn = wid & 3;
    int z = blockIdx.z, bc = z >> 3, hd = z & 7;
    int q0 = blockIdx.y * 64, k0 = blockIdx.x * 128;
    size_t qbase = ((size_t)bc * 512 + q0) * 512 + hd * 64;
    size_t kbase = ((size_t)bc * 512 + k0) * 512 + hd * 64;

    for (int it = tid; it < 512; it += 256) {
        int r = it >> 3, cg = it & 7;
        uint32_t o = SWZ((uint32_t)(r * 128 + cg * 16));
        cp16(sb + o, QTh + qbase + (size_t)r * 512 + cg * 8);
        cp16(sb + 8192 + o, QTl + qbase + (size_t)r * 512 + cg * 8);
    }
    for (int it = tid; it < 1024; it += 256) {
        int r = it >> 3, cg = it & 7;
        uint32_t o = SWZ((uint32_t)(r * 128 + cg * 16));
        cp16(sb + 16384 + o, KTh + kbase + (size_t)r * 512 + cg * 8);
        cp16(sb + 32768 + o, KTl + kbase + (size_t)r * 512 + cg * 8);
    }
    cp_commit(); cp_wait<0>();
    __syncthreads();

    float acc[2][4][4] = {};
    mma_chunk<4>(acc, sb, sb + 8192, sb + 16384, sb + 32768, wm, wn, lane);
    __syncthreads();
    float* stg = (float*)sm;
    #pragma unroll
    for (int mi = 0; mi < 2; mi++)
        #pragma unroll
        for (int nt = 0; nt < 4; nt++) {
            int row = wm * 32 + mi * 16 + (lane >> 2);
            int col = wn * 32 + nt * 8 + (lane & 3) * 2;
            stg[row * 132 + col] = acc[mi][nt][0];
            stg[row * 132 + col + 1] = acc[mi][nt][1];
            stg[(row + 8) * 132 + col] = acc[mi][nt][2];
            stg[(row + 8) * 132 + col + 1] = acc[mi][nt][3];
        }
    __syncthreads();
    const float scale = 0.044194173824159216f;  // 1/sqrt(512)
    int row = tid >> 2, seg = tid & 3;
    float lsum = 0.f;
    u16 hb[32];
    #pragma unroll
    for (int j = 0; j < 32; j++) {
        float p = __expf(stg[row * 132 + seg * 32 + j] * scale);
        lsum += p;
        hb[j] = f2h(p);
    }
    size_t o = (size_t)z * 262144 + (size_t)(q0 + row) * 512 + k0 + seg * 32;
    #pragma unroll
    for (int t = 0; t < 4; t++)
        reinterpret_cast<uint4*>(Ph + o)[t] = ((uint4*)hb)[t];
    lsum += __shfl_xor_sync(0xffffffffu, lsum, 1);
    lsum += __shfl_xor_sync(0xffffffffu, lsum, 2);
    if (seg == 0) atomicAdd(&rowsum[z * 512 + q0 + row], lsum);
}

// ---------------- attention output: P fp16 x V fp16 hi/lo, /rowsum -----------
__global__ void __launch_bounds__(256, 2) attn_pv_bb(
    const u16* __restrict__ Ph,
    const u16* __restrict__ Vh, const u16* __restrict__ Vl,
    const float* __restrict__ rowsum, u16* __restrict__ OT)
{
    extern __shared__ char sm[];
    uint32_t sb = smem_u32(sm);
    int tid = threadIdx.x, wid = tid >> 5, lane = tid & 31;
    int wm = wid >> 2, wn = wid & 3;
    int z = blockIdx.z, bc = z >> 3, hd = z & 7;
    int q0 = blockIdx.x * 64;
    size_t pbase = ((size_t)z * 512 + q0) * 512;
    size_t vbase = ((size_t)bc * 512 + hd * 64) * 512;

    auto load_stage = [&](int ch, int s) {
        uint32_t st = sb + s * 24576;
        for (int it = tid; it < 512; it += 256) {
            int r = it >> 3, cg = it & 7;
            uint32_t o = SWZ((uint32_t)(r * 128 + cg * 16));
            size_t pof = pbase + (size_t)r * 512 + ch * 64 + cg * 8;
            size_t vof = vbase + (size_t)r * 512 + ch * 64 + cg * 8;
            cp16(st + o, Ph + pof);
            cp16(st + 8192 + o, Vh + vof);
            cp16(st + 16384 + o, Vl + vof);
        }
    };

    float acc[2][2][4] = {};
    load_stage(0, 0); cp_commit();
    for (int ch = 0; ch < 8; ch++) {
        if (ch + 1 < 8) { load_stage(ch + 1, (ch + 1) & 1); cp_commit(); cp_wait<1>(); }
        else cp_wait<0>();
        __syncthreads();
        uint32_t st = sb + (ch & 1) * 24576;
        mma2b_chunk<2>(acc, st, st + 8192, st + 16384, wm, wn, lane);
        __syncthreads();
    }
    float* stg = (float*)sm;  // 64 x 68
    #pragma unroll
    for (int mi = 0; mi < 2; mi++)
        #pragma unroll
        for (int nt = 0; nt < 2; nt++) {
            int row = wm * 32 + mi * 16 + (lane >> 2);
            int col = wn * 16 + nt * 8 + (lane & 3) * 2;
            stg[row * 68 + col] = acc[mi][nt][0];
            stg[row * 68 + col + 1] = acc[mi][nt][1];
            stg[(row + 8) * 68 + col] = acc[mi][nt][2];
            stg[(row + 8) * 68 + col + 1] = acc[mi][nt][3];
        }
    __syncthreads();
    int row = tid >> 2, dseg = tid & 3;
    float inv = 1.f / rowsum[z * 512 + q0 + row];
    u16 hb[16];
    #pragma unroll
    for (int j = 0; j < 16; j++) hb[j] = f2h(stg[row * 68 + dseg * 16 + j] * inv);
    size_t o = ((size_t)bc * 512 + q0 + row) * 512 + hd * 64 + dseg * 16;
    reinterpret_cast<uint4*>(OT + o)[0] = ((uint4*)hb)[0];
    reinterpret_cast<uint4*>(OT + o)[1] = ((uint4*)hb)[1];
}

// ---------------- channel mix (enc/dec, f32) ---------------------------------
template<bool SQRELU, bool HASADD>
__global__ void __launch_bounds__(256) mix_k(
    const float* __restrict__ X, const float* __restrict__ dw,
    const float* __restrict__ Add, float* __restrict__ Y, int Fd)
{
    int idx = blockIdx.x * 256 + threadIdx.x;
    int w = idx & 511;
    int f = (idx >> 9) % Fd;
    int bd = idx / (512 * Fd);
    int b = bd >> 1, d = bd & 1;
    size_t base = ((size_t)(b * 2) * Fd + f) * 512 + w;
    float v = dw[d * 2 + 0] * X[base] + dw[d * 2 + 1] * X[base + (size_t)Fd * 512];
    if (SQRELU) { float r = fmaxf(v, 0.f); v = r * r; }
    if (HASADD) v += Add[idx];
    Y[idx] = v;
}

// ---------------- host --------------------------------------------------------
extern "C" void kernel_launch(void* const* d_in, const int* in_sizes, int n_in,
                              void* d_out, int out_size)
{
    const float* x     = (const float*)d_in[0];
    const float* e1_pw = (const float*)d_in[1];
    const float* e1_dw = (const float*)d_in[2];
    const float* e2_pw = (const float*)d_in[3];
    const float* e2_dw = (const float*)d_in[4];
    const float* ei_pw = (const float*)d_in[5];
    const float* ei_dw = (const float*)d_in[6];
    const float* n1_w  = (const float*)d_in[7];
    const float* n1_b  = (const float*)d_in[8];
    const float* q_dw  = (const float*)d_in[10];
    const float* k_dw  = (const float*)d_in[12];
    const float* v_dw  = (const float*)d_in[14];
    const float* n2_w  = (const float*)d_in[16];
    const float* n2_b  = (const float*)d_in[17];
    const float* d1_dw = (const float*)d_in[21];
    const float* d2_dw = (const float*)d_in[23];
    const float* di_dw = (const float*)d_in[25];
    float* out = (float*)d_out;
    (void)in_sizes; (void)n_in; (void)out_size;

    float *e, *q, *big, *s, *rowsum;
    cudaGetSymbolAddress((void**)&e, g_e);
    cudaGetSymbolAddress((void**)&q, g_q);
    cudaGetSymbolAddress((void**)&big, g_big);
    cudaGetSymbolAddress((void**)&s, g_s);
    cudaGetSymbolAddress((void**)&rowsum, g_rowsum);
    u16 *wh, *wl, *cqh, *cql, *ath, *hth, *oth, *qth, *qtl, *kth, *ktl, *vh, *vl, *ph;
    cudaGetSymbolAddress((void**)&wh, g_wh);   cudaGetSymbolAddress((void**)&wl, g_wl);
    cudaGetSymbolAddress((void**)&cqh, g_cqh); cudaGetSymbolAddress((void**)&cql, g_cql);
    cudaGetSymbolAddress((void**)&ath, g_ath);
    cudaGetSymbolAddress((void**)&hth, g_hth);
    cudaGetSymbolAddress((void**)&oth, g_oth);
    cudaGetSymbolAddress((void**)&qth, g_qth); cudaGetSymbolAddress((void**)&qtl, g_qtl);
    cudaGetSymbolAddress((void**)&kth, g_kth); cudaGetSymbolAddress((void**)&ktl, g_ktl);
    cudaGetSymbolAddress((void**)&vh, g_vh);   cudaGetSymbolAddress((void**)&vl, g_vl);
    cudaGetSymbolAddress((void**)&ph, g_ph);

    const int SMG4 = 65536, SMG2 = 49152, SMPV = 49152, SMQKV = 65536;
    cudaFuncSetAttribute(gemm_bb<0,4>, cudaFuncAttributeMaxDynamicSharedMemorySize, SMG4);
    cudaFuncSetAttribute(gemm_bb<3,4>, cudaFuncAttributeMaxDynamicSharedMemorySize, SMG4);
    cudaFuncSetAttribute(gemm_bb<0,2>, cudaFuncAttributeMaxDynamicSharedMemorySize, SMG2);
    cudaFuncSetAttribute(gemm_bb<2,2>, cudaFuncAttributeMaxDynamicSharedMemorySize, SMG2);
    cudaFuncSetAttribute(gemm_qkv, cudaFuncAttributeMaxDynamicSharedMemorySize, SMQKV);
    cudaFuncSetAttribute(attn_pv_bb, cudaFuncAttributeMaxDynamicSharedMemorySize, SMPV);

    dim3 tsG512(8, 8, 4), tsG1024(8, 16, 4);

    split_w<<<20096, 256>>>(e1_pw, e2_pw, ei_pw,
        (const float*)d_in[9], (const float*)d_in[11], (const float*)d_in[13],
        (const float*)d_in[15], (const float*)d_in[18], (const float*)d_in[19],
        (const float*)d_in[20], (const float*)d_in[22], (const float*)d_in[24]);
    split_qkv<<<9216, 256>>>(
        (const float*)d_in[9], (const float*)d_in[11], (const float*)d_in[13],
        q_dw, k_dw, v_dw);

    // encoder (BN=64: 256 blocks per launch)
    tsplit<<<tsG1024, 256>>>(x, ath, 1024);
    gemm_bb<0,2><<<dim3(8, 8, 4), 256, SMG2>>>(wh + OFF_E1, wl + OFF_E1, ath, nullptr, big, nullptr, 512, 1024, 1024, 1048576, 524288);
    mix_k<true, false><<<4096, 256>>>(big, e1_dw, nullptr, q, 512);
    tsplit<<<tsG512, 256>>>(q, hth, 512);
    gemm_bb<0,2><<<dim3(8, 8, 4), 256, SMG2>>>(wh + OFF_E2, wl + OFF_E2, hth, nullptr, big, nullptr, 512, 512, 512, 524288, 262144);
    mix_k<false, false><<<4096, 256>>>(big, e2_dw, nullptr, s, 512);
    gemm_bb<0,2><<<dim3(8, 8, 4), 256, SMG2>>>(wh + OFF_EI, wl + OFF_EI, ath, nullptr, big, nullptr, 512, 1024, 1024, 1048576, 524288);
    mix_k<false, true><<<4096, 256>>>(big, ei_dw, s, e, 512);

    for (int i = 0; i < NLAYER; i++) {
        long lw = (long)i * 524288;
        long lcq = (long)i * 3145728;
        fn_tsplit<<<dim3(8, 8, 4), 256>>>(e, n1_w + (size_t)i * 1024, n1_b + (size_t)i * 1024, hth, rowsum);
        gemm_qkv<<<dim3(4, 8, 12), 256, SMQKV>>>(cqh + lcq, cql + lcq, hth,
                                                 qth, qtl, kth, ktl, vh, vl);
        attn_qk_bb<<<dim3(4, 8, 32), 256>>>(qth, qtl, kth, ktl, ph, rowsum);
        attn_pv_bb<<<dim3(8, 1, 32), 256, SMPV>>>(ph, vh, vl, rowsum, oth);
        gemm_bb<2,2><<<dim3(8, 8, 4), 256, SMG2>>>(wh + OFF_O + lw, wl + OFF_O + lw, oth,
                                                   e, e, nullptr, 512, 512, 512, 524288, 262144);
        fn_tsplit<<<dim3(8, 8, 4), 256>>>(e, n2_w + (size_t)i * 1024, n2_b + (size_t)i * 1024, hth, rowsum);
        long lf = (long)i * 2097152;
        gemm_bb<3,4><<<dim3(4, 32, 4), 256, SMG4>>>(wh + OFF_F1 + lf, wl + OFF_F1 + lf, hth,
                                                    nullptr, nullptr, ath, 2048, 512, 1024, 524288, 512);
        gemm_bb<2,2><<<dim3(8, 8, 4), 256, SMG2>>>(wh + OFF_F2 + lf, wl + OFF_F2 + lf, ath,
                                                   e, e, nullptr, 512, 2048, 2048, 2097152, 1048576);
    }

    // decoder (BN=64: 512 blocks per launch)
    tsplit<<<tsG512, 256>>>(e, hth, 512);
    gemm_bb<0,2><<<dim3(8, 16, 4), 256, SMG2>>>(wh + OFF_D1, wl + OFF_D1, hth, nullptr, big, nullptr, 1024, 512, 512, 524288, 262144);
    mix_k<true, false><<<8192, 256>>>(big, d1_dw, nullptr, s, 1024);
    tsplit<<<tsG1024, 256>>>(s, ath, 1024);
    gemm_bb<0,2><<<dim3(8, 16, 4), 256, SMG2>>>(wh + OFF_D2, wl + OFF_D2, ath, nullptr, big + 2097152, nullptr, 1024, 1024, 1024, 1048576, 524288);
    mix_k<false, false><<<8192, 256>>>(big + 2097152, d2_dw, nullptr, s + 4194304, 1024);
    gemm_bb<0,2><<<dim3(8, 16, 4), 256, SMG2>>>(wh + OFF_DI, wl + OFF_DI, hth, nullptr, big, nullptr, 1024, 512, 512, 524288, 262144);
    mix_k<false, true><<<8192, 256>>>(big, di_dw, s + 4194304, out, 1024);
}